// round 14
// baseline (speedup 1.0000x reference)
#include <cuda_runtime.h>
#include <math.h>
#include <stdint.h>

#define N_   32
#define C_   512
#define HW_  4096          // 64*64
#define D_   4
#define BLK_ 128           // C_/D_
#define HID_ 32            // C_/16
#define CD_  (C_ * D_)     // 2048
#define G_   4             // samples per L2-resident group
#define NGRP (N_ / G_)     // 8 groups

// ---- scratch (no allocations allowed) ----
__device__ float g_avgp[N_ * C_];
__device__ float g_maxp[N_ * C_];
__device__ int   g_idx [N_ * C_];   // selected channels, output order

// ---------------------------------------------------------------------------
// K1: pooling for one group of G_ samples. Default-cached loads: we WANT the
// group's x resident in L2 for the gather that follows two launches later.
// ---------------------------------------------------------------------------
__global__ __launch_bounds__(256) void pool_kernel(
    const float* __restrict__ x, int base_row) {
    const int row = base_row + blockIdx.x;           // n*C + c
    const float4* xr = reinterpret_cast<const float4*>(x + (size_t)row * HW_);

    float s = 0.0f;
    float m = -INFINITY;
    #pragma unroll 4
    for (int i = threadIdx.x; i < HW_ / 4; i += 256) {
        float4 v = xr[i];
        s += (v.x + v.y) + (v.z + v.w);
        m = fmaxf(m, fmaxf(fmaxf(v.x, v.y), fmaxf(v.z, v.w)));
    }
    #pragma unroll
    for (int off = 16; off > 0; off >>= 1) {
        s += __shfl_xor_sync(0xffffffffu, s, off);
        m = fmaxf(m, __shfl_xor_sync(0xffffffffu, m, off));
    }
    __shared__ float ss[8], sm[8];
    const int wid = threadIdx.x >> 5;
    const int lid = threadIdx.x & 31;
    if (lid == 0) { ss[wid] = s; sm[wid] = m; }
    __syncthreads();
    if (threadIdx.x == 0) {
        float ts = ss[0], tm = sm[0];
        #pragma unroll
        for (int w = 1; w < 8; w++) { ts += ss[w]; tm = fmaxf(tm, sm[w]); }
        g_avgp[row] = ts * (1.0f / HW_);
        g_maxp[row] = tm;
    }
}

// ---------------------------------------------------------------------------
// K2: fused MLP + sigmoid + top-128 rank for one group. One block per (n, d).
//   key = (bits(sigmoid)<<16) | (65535-c): sigmoid>0 -> monotone float bits;
//   low-bits index tiebreak = exact lax.top_k order.
// ---------------------------------------------------------------------------
__global__ __launch_bounds__(512) void mlp_rank_kernel(
    const float* __restrict__ W1, const float* __restrict__ b1,
    const float* __restrict__ W2, const float* __restrict__ b2,
    int base_task) {
    const int b   = base_task + blockIdx.x;          // n*D + d
    const int n   = b >> 2;
    const int d   = b & 3;
    const int tid = threadIdx.x;
    const int w   = tid >> 5;        // warp 0..15
    const int j   = tid & 31;        // lane = hidden index

    __shared__ float avg_s[C_];
    __shared__ float max_s[C_];
    __shared__ float part_a[16 * HID_];
    __shared__ float part_m[16 * HID_];
    __shared__ float hs[HID_];
    __shared__ unsigned long long keys[C_];

    avg_s[tid] = g_avgp[n * C_ + tid];
    max_s[tid] = g_maxp[n * C_ + tid];
    __syncthreads();

    // Layer 1, coalesced: warp w handles channels c = w, w+16, ...
    {
        float sa = 0.0f, smx = 0.0f;
        #pragma unroll 8
        for (int c = w; c < C_; c += 16) {
            float w1 = W1[c * HID_ + j];
            sa  = fmaf(avg_s[c], w1, sa);
            smx = fmaf(max_s[c], w1, smx);
        }
        part_a[w * HID_ + j] = sa;
        part_m[w * HID_ + j] = smx;
    }
    __syncthreads();
    if (tid < HID_) {
        float sa = 0.0f, smx = 0.0f;
        #pragma unroll
        for (int ww = 0; ww < 16; ww++) {
            sa  += part_a[ww * HID_ + tid];
            smx += part_m[ww * HID_ + tid];
        }
        float bb = b1[tid];
        hs[tid] = fmaxf(sa + bb, 0.0f) + fmaxf(smx + bb, 0.0f);
    }
    __syncthreads();

    // Layer 2 + sigmoid + key: thread c computes output o = c*4 + d.
    {
        const int c = tid;
        const int o = c * D_ + d;
        float acc = 2.0f * b2[o];
        #pragma unroll
        for (int k = 0; k < HID_; k++)
            acc = fmaf(hs[k], W2[k * CD_ + o], acc);
        float v = 1.0f / (1.0f + expf(-acc));
        keys[c] = ((unsigned long long)__float_as_uint(v) << 16) |
                  (unsigned long long)(65535 - c);
    }
    __syncthreads();

    // Rank by count.
    {
        const unsigned long long myk = keys[tid];
        int rank = 0;
        const ulonglong2* k2 = reinterpret_cast<const ulonglong2*>(keys);
        #pragma unroll 8
        for (int i = 0; i < C_ / 2; i++) {
            ulonglong2 u = k2[i];
            rank += (u.x > myk) + (u.y > myk);
        }
        if (rank < BLK_)
            g_idx[n * C_ + d * BLK_ + rank] = tid;
    }
}

// ---------------------------------------------------------------------------
// K3: gather for one group. Reads hit L2 (group x loaded by pool two launches
// earlier, 67 MB worst-case working set < 126 MB L2). Writes streaming so the
// out stream doesn't evict the resident x.
// ---------------------------------------------------------------------------
__global__ __launch_bounds__(256) void gather_kernel(
    const float* __restrict__ x, float* __restrict__ out, int base_row) {
    const int row = base_row + blockIdx.x;           // n*512 + j
    const int n   = row >> 9;
    const int c   = g_idx[row];
    const float4* src = reinterpret_cast<const float4*>(
        x + ((size_t)n * C_ + c) * HW_);
    float4* dst = reinterpret_cast<float4*>(out + (size_t)row * HW_);
    #pragma unroll 4
    for (int i = threadIdx.x; i < HW_ / 4; i += 256) {
        float4 v = src[i];
        __stcs(dst + i, v);
    }
}

extern "C" void kernel_launch(void* const* d_in, const int* in_sizes, int n_in,
                              void* d_out, int out_size) {
    const float* x  = (const float*)d_in[0];
    const float* W1 = (const float*)d_in[1];
    const float* b1 = (const float*)d_in[2];
    const float* W2 = (const float*)d_in[3];
    const float* b2 = (const float*)d_in[4];
    float* out = (float*)d_out;

    const int ROWS_G  = G_ * C_;   // 2048 rows per group
    const int TASKS_G = G_ * D_;   // 16 mlp tasks per group

    // Software-pipelined group schedule (single stream, graph-capturable):
    //   pool(0), mlp(0), { pool(g), gather(g-1), mlp(g) }, gather(last)
    pool_kernel<<<ROWS_G, 256>>>(x, 0);
    mlp_rank_kernel<<<TASKS_G, 512>>>(W1, b1, W2, b2, 0);
    for (int g = 1; g < NGRP; g++) {
        pool_kernel<<<ROWS_G, 256>>>(x, g * ROWS_G);
        gather_kernel<<<ROWS_G, 256>>>(x, out, (g - 1) * ROWS_G);
        mlp_rank_kernel<<<TASKS_G, 512>>>(W1, b1, W2, b2, g * TASKS_G);
    }
    gather_kernel<<<ROWS_G, 256>>>(x, out, (NGRP - 1) * ROWS_G);
}

// round 15
// speedup vs baseline: 1.0821x; 1.0821x over previous
#include <cuda_runtime.h>
#include <math.h>
#include <stdint.h>

#define N_   32
#define C_   512
#define HW_  4096          // 64*64
#define D_   4
#define BLK_ 128           // C_/D_
#define HID_ 32            // C_/16
#define CD_  (C_ * D_)     // 2048
#define G_   4             // samples per L2-resident group
#define NGRP (N_ / G_)     // 8 groups

// ---- scratch (no allocations allowed) ----
__device__ float g_avgp[N_ * C_];
__device__ float g_maxp[N_ * C_];
__device__ int   g_idx [N_ * C_];   // selected channels, output order

// ---------------------------------------------------------------------------
// K1: pooling for one group. Default-cached loads: group x stays in L2 for
// the concurrent gather of the previous group / upcoming gather of this one.
// ---------------------------------------------------------------------------
__global__ __launch_bounds__(256) void pool_kernel(
    const float* __restrict__ x, int base_row) {
    const int row = base_row + blockIdx.x;           // n*C + c
    const float4* xr = reinterpret_cast<const float4*>(x + (size_t)row * HW_);

    float s = 0.0f;
    float m = -INFINITY;
    #pragma unroll 4
    for (int i = threadIdx.x; i < HW_ / 4; i += 256) {
        float4 v = xr[i];
        s += (v.x + v.y) + (v.z + v.w);
        m = fmaxf(m, fmaxf(fmaxf(v.x, v.y), fmaxf(v.z, v.w)));
    }
    #pragma unroll
    for (int off = 16; off > 0; off >>= 1) {
        s += __shfl_xor_sync(0xffffffffu, s, off);
        m = fmaxf(m, __shfl_xor_sync(0xffffffffu, m, off));
    }
    __shared__ float ss[8], sm[8];
    const int wid = threadIdx.x >> 5;
    const int lid = threadIdx.x & 31;
    if (lid == 0) { ss[wid] = s; sm[wid] = m; }
    __syncthreads();
    if (threadIdx.x == 0) {
        float ts = ss[0], tm = sm[0];
        #pragma unroll
        for (int w = 1; w < 8; w++) { ts += ss[w]; tm = fmaxf(tm, sm[w]); }
        g_avgp[row] = ts * (1.0f / HW_);
        g_maxp[row] = tm;
    }
}

// ---------------------------------------------------------------------------
// K2: fused MLP + sigmoid + top-128 rank for one group. One block per (n, d).
//   key = (bits(sigmoid)<<16) | (65535-c): sigmoid>0 -> monotone float bits;
//   low-bits index tiebreak = exact lax.top_k order.
// ---------------------------------------------------------------------------
__global__ __launch_bounds__(512) void mlp_rank_kernel(
    const float* __restrict__ W1, const float* __restrict__ b1,
    const float* __restrict__ W2, const float* __restrict__ b2,
    int base_task) {
    const int b   = base_task + blockIdx.x;          // n*D + d
    const int n   = b >> 2;
    const int d   = b & 3;
    const int tid = threadIdx.x;
    const int w   = tid >> 5;        // warp 0..15
    const int j   = tid & 31;        // lane = hidden index

    __shared__ float avg_s[C_];
    __shared__ float max_s[C_];
    __shared__ float part_a[16 * HID_];
    __shared__ float part_m[16 * HID_];
    __shared__ float hs[HID_];
    __shared__ unsigned long long keys[C_];

    avg_s[tid] = g_avgp[n * C_ + tid];
    max_s[tid] = g_maxp[n * C_ + tid];
    __syncthreads();

    // Layer 1, coalesced: warp w handles channels c = w, w+16, ...
    {
        float sa = 0.0f, smx = 0.0f;
        #pragma unroll 8
        for (int c = w; c < C_; c += 16) {
            float w1 = W1[c * HID_ + j];
            sa  = fmaf(avg_s[c], w1, sa);
            smx = fmaf(max_s[c], w1, smx);
        }
        part_a[w * HID_ + j] = sa;
        part_m[w * HID_ + j] = smx;
    }
    __syncthreads();
    if (tid < HID_) {
        float sa = 0.0f, smx = 0.0f;
        #pragma unroll
        for (int ww = 0; ww < 16; ww++) {
            sa  += part_a[ww * HID_ + tid];
            smx += part_m[ww * HID_ + tid];
        }
        float bb = b1[tid];
        hs[tid] = fmaxf(sa + bb, 0.0f) + fmaxf(smx + bb, 0.0f);
    }
    __syncthreads();

    // Layer 2 + sigmoid + key: thread c computes output o = c*4 + d.
    {
        const int c = tid;
        const int o = c * D_ + d;
        float acc = 2.0f * b2[o];
        #pragma unroll
        for (int k = 0; k < HID_; k++)
            acc = fmaf(hs[k], W2[k * CD_ + o], acc);
        float v = 1.0f / (1.0f + expf(-acc));
        keys[c] = ((unsigned long long)__float_as_uint(v) << 16) |
                  (unsigned long long)(65535 - c);
    }
    __syncthreads();

    // Rank by count.
    {
        const unsigned long long myk = keys[tid];
        int rank = 0;
        const ulonglong2* k2 = reinterpret_cast<const ulonglong2*>(keys);
        #pragma unroll 8
        for (int i = 0; i < C_ / 2; i++) {
            ulonglong2 u = k2[i];
            rank += (u.x > myk) + (u.y > myk);
        }
        if (rank < BLK_)
            g_idx[n * C_ + d * BLK_ + rank] = tid;
    }
}

// ---------------------------------------------------------------------------
// K3: gather for one group. Reads are L2 hits (group x loaded by pool just
// before); __ldcs = last touch, evict-first frees space for the next group.
// __stcs keeps the write stream from evicting resident x.
// ---------------------------------------------------------------------------
__global__ __launch_bounds__(256) void gather_kernel(
    const float* __restrict__ x, float* __restrict__ out, int base_row) {
    const int row = base_row + blockIdx.x;           // n*512 + j
    const int n   = row >> 9;
    const int c   = g_idx[row];
    const float4* src = reinterpret_cast<const float4*>(
        x + ((size_t)n * C_ + c) * HW_);
    float4* dst = reinterpret_cast<float4*>(out + (size_t)row * HW_);
    #pragma unroll 4
    for (int i = threadIdx.x; i < HW_ / 4; i += 256) {
        float4 v = __ldcs(src + i);
        __stcs(dst + i, v);
    }
}

extern "C" void kernel_launch(void* const* d_in, const int* in_sizes, int n_in,
                              void* d_out, int out_size) {
    const float* x  = (const float*)d_in[0];
    const float* W1 = (const float*)d_in[1];
    const float* b1 = (const float*)d_in[2];
    const float* W2 = (const float*)d_in[3];
    const float* b2 = (const float*)d_in[4];
    float* out = (float*)d_out;

    // One-time host-object setup (streams/events are NOT device memory).
    static cudaStream_t s1 = nullptr;
    static cudaEvent_t  ev_pool[NGRP];
    static cudaEvent_t  ev_join;
    if (s1 == nullptr) {
        cudaStreamCreateWithFlags(&s1, cudaStreamNonBlocking);
        for (int g = 0; g < NGRP; g++)
            cudaEventCreateWithFlags(&ev_pool[g], cudaEventDisableTiming);
        cudaEventCreateWithFlags(&ev_join, cudaEventDisableTiming);
    }

    const int ROWS_G  = G_ * C_;   // 2048 rows per group
    const int TASKS_G = G_ * D_;   // 16 mlp tasks per group

    // Stream 0: the pool pipeline (keeps DRAM read stream saturated).
    for (int g = 0; g < NGRP; g++) {
        pool_kernel<<<ROWS_G, 256, 0, 0>>>(x, g * ROWS_G);
        cudaEventRecord(ev_pool[g], 0);
    }
    // Stream s1: per-group mlp+rank then gather, chasing pool's progress.
    // gather(g) runs concurrent with pool(g+1): reads hit L2, writes go to DRAM.
    for (int g = 0; g < NGRP; g++) {
        cudaStreamWaitEvent(s1, ev_pool[g], 0);
        mlp_rank_kernel<<<TASKS_G, 512, 0, s1>>>(W1, b1, W2, b2, g * TASKS_G);
        gather_kernel<<<ROWS_G, 256, 0, s1>>>(x, out, g * ROWS_G);
    }
    // Join the forked stream back so the captured graph has a single tail.
    cudaEventRecord(ev_join, s1);
    cudaStreamWaitEvent(0, ev_join, 0);
}

// round 16
// speedup vs baseline: 1.7503x; 1.6176x over previous
#include <cuda_runtime.h>
#include <math.h>
#include <stdint.h>

#define N_   32
#define C_   512
#define HW_  4096          // 64*64
#define D_   4
#define BLK_ 128           // C_/D_
#define HID_ 32            // C_/16
#define CD_  (C_ * D_)     // 2048
#define HALF_SAMP (N_ / 2)           // 16 samples per half
#define HALF_ROWS (HALF_SAMP * C_)   // 8192 rows per half (~7 waves)
#define HALF_TASK (HALF_SAMP * D_)   // 64 mlp tasks per half

// ---- scratch (no allocations allowed) ----
__device__ float g_avgp[N_ * C_];
__device__ float g_maxp[N_ * C_];
__device__ int   g_idx [N_ * C_];   // selected channels, output order

// ---------------------------------------------------------------------------
// K1: pooling for one half (8192 rows). Default-cached loads — we WANT this
// half's x resident in L2 for the gather that follows immediately.
// ---------------------------------------------------------------------------
__global__ __launch_bounds__(256) void pool_kernel(
    const float* __restrict__ x, int base_row) {
    const int row = base_row + blockIdx.x;           // n*C + c
    const float4* xr = reinterpret_cast<const float4*>(x + (size_t)row * HW_);

    float s = 0.0f;
    float m = -INFINITY;
    #pragma unroll 4
    for (int i = threadIdx.x; i < HW_ / 4; i += 256) {
        float4 v = xr[i];
        s += (v.x + v.y) + (v.z + v.w);
        m = fmaxf(m, fmaxf(fmaxf(v.x, v.y), fmaxf(v.z, v.w)));
    }
    #pragma unroll
    for (int off = 16; off > 0; off >>= 1) {
        s += __shfl_xor_sync(0xffffffffu, s, off);
        m = fmaxf(m, __shfl_xor_sync(0xffffffffu, m, off));
    }
    __shared__ float ss[8], sm[8];
    const int wid = threadIdx.x >> 5;
    const int lid = threadIdx.x & 31;
    if (lid == 0) { ss[wid] = s; sm[wid] = m; }
    __syncthreads();
    if (threadIdx.x == 0) {
        float ts = ss[0], tm = sm[0];
        #pragma unroll
        for (int w = 1; w < 8; w++) { ts += ss[w]; tm = fmaxf(tm, sm[w]); }
        g_avgp[row] = ts * (1.0f / HW_);
        g_maxp[row] = tm;
    }
}

// ---------------------------------------------------------------------------
// K2: fused MLP + sigmoid + top-128 rank for one half. One block per (n, d).
//   key = (bits(sigmoid)<<16) | (65535-c): sigmoid>0 -> monotone float bits;
//   low-bits index tiebreak = exact lax.top_k order.
// ---------------------------------------------------------------------------
__global__ __launch_bounds__(512) void mlp_rank_kernel(
    const float* __restrict__ W1, const float* __restrict__ b1,
    const float* __restrict__ W2, const float* __restrict__ b2,
    int base_task) {
    const int b   = base_task + blockIdx.x;          // n*D + d
    const int n   = b >> 2;
    const int d   = b & 3;
    const int tid = threadIdx.x;
    const int w   = tid >> 5;        // warp 0..15
    const int j   = tid & 31;        // lane = hidden index

    __shared__ float avg_s[C_];
    __shared__ float max_s[C_];
    __shared__ float part_a[16 * HID_];
    __shared__ float part_m[16 * HID_];
    __shared__ float hs[HID_];
    __shared__ unsigned long long keys[C_];

    avg_s[tid] = g_avgp[n * C_ + tid];
    max_s[tid] = g_maxp[n * C_ + tid];
    __syncthreads();

    // Layer 1, coalesced: warp w handles channels c = w, w+16, ...
    {
        float sa = 0.0f, smx = 0.0f;
        #pragma unroll 8
        for (int c = w; c < C_; c += 16) {
            float w1 = W1[c * HID_ + j];
            sa  = fmaf(avg_s[c], w1, sa);
            smx = fmaf(max_s[c], w1, smx);
        }
        part_a[w * HID_ + j] = sa;
        part_m[w * HID_ + j] = smx;
    }
    __syncthreads();
    if (tid < HID_) {
        float sa = 0.0f, smx = 0.0f;
        #pragma unroll
        for (int ww = 0; ww < 16; ww++) {
            sa  += part_a[ww * HID_ + tid];
            smx += part_m[ww * HID_ + tid];
        }
        float bb = b1[tid];
        hs[tid] = fmaxf(sa + bb, 0.0f) + fmaxf(smx + bb, 0.0f);
    }
    __syncthreads();

    // Layer 2 + sigmoid + key: thread c computes output o = c*4 + d.
    {
        const int c = tid;
        const int o = c * D_ + d;
        float acc = 2.0f * b2[o];
        #pragma unroll
        for (int k = 0; k < HID_; k++)
            acc = fmaf(hs[k], W2[k * CD_ + o], acc);
        float v = 1.0f / (1.0f + expf(-acc));
        keys[c] = ((unsigned long long)__float_as_uint(v) << 16) |
                  (unsigned long long)(65535 - c);
    }
    __syncthreads();

    // Rank by count.
    {
        const unsigned long long myk = keys[tid];
        int rank = 0;
        const ulonglong2* k2 = reinterpret_cast<const ulonglong2*>(keys);
        #pragma unroll 8
        for (int i = 0; i < C_ / 2; i++) {
            ulonglong2 u = k2[i];
            rank += (u.x > myk) + (u.y > myk);
        }
        if (rank < BLK_)
            g_idx[n * C_ + d * BLK_ + rank] = tid;
    }
}

// ---------------------------------------------------------------------------
// K3: gather for one half, DESCENDING row order within the half: last-pooled
// sample is gathered first while its x lines are hottest in L2. __ldcs reads
// (last touch, evict-first), __stcs writes (don't evict resident x).
// ---------------------------------------------------------------------------
__global__ __launch_bounds__(256) void gather_kernel(
    const float* __restrict__ x, float* __restrict__ out, int base_row) {
    const int row = base_row + (HALF_ROWS - 1 - blockIdx.x);   // descending
    const int n   = row >> 9;
    const int c   = g_idx[row];
    const float4* src = reinterpret_cast<const float4*>(
        x + ((size_t)n * C_ + c) * HW_);
    float4* dst = reinterpret_cast<float4*>(out + (size_t)row * HW_);
    #pragma unroll 4
    for (int i = threadIdx.x; i < HW_ / 4; i += 256) {
        float4 v = __ldcs(src + i);
        __stcs(dst + i, v);
    }
}

extern "C" void kernel_launch(void* const* d_in, const int* in_sizes, int n_in,
                              void* d_out, int out_size) {
    const float* x  = (const float*)d_in[0];
    const float* W1 = (const float*)d_in[1];
    const float* b1 = (const float*)d_in[2];
    const float* W2 = (const float*)d_in[3];
    const float* b2 = (const float*)d_in[4];
    float* out = (float*)d_out;

    // Sequential half-pipeline: each half's gather runs right after its pool,
    // while that half's x (~134 MB) is still L2-resident. Full-size grids
    // (8192 blocks ~ 7 waves) keep every kernel at its DRAM roofline.
    for (int h = 0; h < 2; h++) {
        pool_kernel<<<HALF_ROWS, 256>>>(x, h * HALF_ROWS);
        mlp_rank_kernel<<<HALF_TASK, 512>>>(W1, b1, W2, b2, h * HALF_TASK);
        gather_kernel<<<HALF_ROWS, 256>>>(x, out, h * HALF_ROWS);
    }
}